// round 14
// baseline (speedup 1.0000x reference)
#include <cuda_runtime.h>
#include <math.h>

// Shapes
#define NB 256            // batch
#define NF 4              // frames
#define PIX4 9408         // float4 per frame (3*112*112/4)
#define TPB 256
#define CH 4096           // float4 per block: 256*9408 = 588*4096 exactly
#define GRID 588

// Scratch. g_part/g_neq: zero at process start; epilogue re-zeroes after use.
__device__ float g_part[NB * 3];
__device__ int   g_neq[NB];
__device__ float g_cos[NB * 3];
__device__ int   g_ctr;

__global__ void __launch_bounds__(TPB, 6)
fused_kernel(const float4* __restrict__ img,
             const float* __restrict__ feat,
             const float* __restrict__ feat_norm,
             float* __restrict__ out) {
    __shared__ float sm7[7][TPB / 32];
    __shared__ int   smn[TPB / 32];
    __shared__ int   s_last;

    const int w = threadIdx.x >> 5;
    const int l = threadIdx.x & 31;

    // ---------------- feat prelude (blocks 0..255 only) -------------------
    if (blockIdx.x < NB) {
        const int b = blockIdx.x;
        const float* fb = feat + (size_t)b * (NF * 512);

        float n0 = 0.f, n1 = 0.f, n2 = 0.f, n3 = 0.f;
        float d01 = 0.f, d12 = 0.f, d23 = 0.f;
        #pragma unroll
        for (int k = 0; k < 2; k++) {
            int i = threadIdx.x + k * TPB;
            float a = fb[i];
            float c = fb[512 + i];
            float d = fb[1024 + i];
            float e = fb[1536 + i];
            n0 += a * a; n1 += c * c; n2 += d * d; n3 += e * e;
            d01 += a * c; d12 += c * d; d23 += d * e;
        }
        #pragma unroll
        for (int off = 16; off; off >>= 1) {
            n0  += __shfl_down_sync(0xffffffffu, n0,  off);
            n1  += __shfl_down_sync(0xffffffffu, n1,  off);
            n2  += __shfl_down_sync(0xffffffffu, n2,  off);
            n3  += __shfl_down_sync(0xffffffffu, n3,  off);
            d01 += __shfl_down_sync(0xffffffffu, d01, off);
            d12 += __shfl_down_sync(0xffffffffu, d12, off);
            d23 += __shfl_down_sync(0xffffffffu, d23, off);
        }
        if (l == 0) {
            sm7[0][w] = n0;  sm7[1][w] = n1;  sm7[2][w] = n2;  sm7[3][w] = n3;
            sm7[4][w] = d01; sm7[5][w] = d12; sm7[6][w] = d23;
        }
        __syncthreads();
        if (threadIdx.x == 0) {
            float v[7];
            #pragma unroll
            for (int j = 0; j < 7; j++) {
                float s = 0.f;
                #pragma unroll
                for (int k = 0; k < TPB / 32; k++) s += sm7[j][k];
                v[j] = s;
            }
            float na[4];
            #pragma unroll
            for (int j = 0; j < 4; j++) na[j] = fmaxf(sqrtf(v[j]), 1e-8f);
            #pragma unroll
            for (int j = 0; j < 3; j++)
                g_cos[b * 3 + j] = v[4 + j] / (na[j] * na[j + 1]);

            const float fn0 = feat_norm[b * NF];     // feat_norm[b,0,0]
            const bool cond = fn0 > 0.0f;            // TAO = 0
            const float wgt = 1.0f / (expf(fn0) + 1e-10f);
            out[1 + b] = cond ? wgt : 0.0f;          // also encodes cond (wgt>0)
        }
        __syncthreads();   // sm7 reused below
    }

    // ---------------- img chunk: <=2 single-batch ranges ------------------
    {
        const int start = blockIdx.x * CH;
        const int endc = start + CH;
        int r0 = start;
        int bcur = start / PIX4;

        while (r0 < endc) {
            const int r1 = min(endc, (bcur + 1) * PIX4);
            const float4* base = img + (size_t)3 * bcur * PIX4;

            float s1 = 0.f, s2 = 0.f, s3 = 0.f;
            unsigned m1 = 0, m2 = 0, m3 = 0;

            for (int i = r0 + threadIdx.x; i < r1; i += TPB) {
                float4 f0 = __ldcs(base + i);
                float4 f1 = __ldcs(base + i + PIX4);
                float4 f2 = __ldcs(base + i + 2 * PIX4);
                float4 f3 = __ldcs(base + i + 3 * PIX4);

                float dx, dy, dz, dw;
                dx = f1.x - f0.x; dy = f1.y - f0.y; dz = f1.z - f0.z; dw = f1.w - f0.w;
                s1 += dx * dx + dy * dy + dz * dz + dw * dw;
                dx = f2.x - f1.x; dy = f2.y - f1.y; dz = f2.z - f1.z; dw = f2.w - f1.w;
                s2 += dx * dx + dy * dy + dz * dz + dw * dw;
                dx = f3.x - f2.x; dy = f3.y - f2.y; dz = f3.z - f2.z; dw = f3.w - f2.w;
                s3 += dx * dx + dy * dy + dz * dz + dw * dw;

                // neq vs frame 0, bitwise (input has no NaN / +-0 collisions)
                m1 |= (__float_as_uint(f1.x) ^ __float_as_uint(f0.x)) |
                      (__float_as_uint(f1.y) ^ __float_as_uint(f0.y)) |
                      (__float_as_uint(f1.z) ^ __float_as_uint(f0.z)) |
                      (__float_as_uint(f1.w) ^ __float_as_uint(f0.w));
                m2 |= (__float_as_uint(f2.x) ^ __float_as_uint(f0.x)) |
                      (__float_as_uint(f2.y) ^ __float_as_uint(f0.y)) |
                      (__float_as_uint(f2.z) ^ __float_as_uint(f0.z)) |
                      (__float_as_uint(f2.w) ^ __float_as_uint(f0.w));
                m3 |= (__float_as_uint(f3.x) ^ __float_as_uint(f0.x)) |
                      (__float_as_uint(f3.y) ^ __float_as_uint(f0.y)) |
                      (__float_as_uint(f3.z) ^ __float_as_uint(f0.z)) |
                      (__float_as_uint(f3.w) ^ __float_as_uint(f0.w));
            }

            int mp = (m1 ? 1 : 0) | (m2 ? 2 : 0) | (m3 ? 4 : 0);
            #pragma unroll
            for (int off = 16; off; off >>= 1) {
                s1 += __shfl_down_sync(0xffffffffu, s1, off);
                s2 += __shfl_down_sync(0xffffffffu, s2, off);
                s3 += __shfl_down_sync(0xffffffffu, s3, off);
                mp |= __shfl_down_sync(0xffffffffu, mp, off);
            }
            if (l == 0) { sm7[0][w] = s1; sm7[1][w] = s2; sm7[2][w] = s3; smn[w] = mp; }
            __syncthreads();
            if (threadIdx.x == 0) {
                float v0 = 0.f, v1 = 0.f, v2 = 0.f;
                int nq = 0;
                #pragma unroll
                for (int k = 0; k < TPB / 32; k++) {
                    v0 += sm7[0][k]; v1 += sm7[1][k]; v2 += sm7[2][k];
                    nq |= smn[k];
                }
                atomicAdd(&g_part[bcur * 3 + 0], v0);
                atomicAdd(&g_part[bcur * 3 + 1], v1);
                atomicAdd(&g_part[bcur * 3 + 2], v2);
                atomicOr(&g_neq[bcur], nq);
            }
            __syncthreads();   // smem reuse if a 2nd range follows
            r0 = r1;
            bcur++;
        }
    }

    // ---------------- elect last-finished block for the epilogue ----------
    if (threadIdx.x == 0) {
        __threadfence();
        int old = atomicAdd(&g_ctr, 1);
        s_last = (old == GRID - 1) ? 1 : 0;
    }
    __syncthreads();
    if (!s_last) return;

    __threadfence();  // acquire: all other blocks' atomics/stores visible

    // thread b handles batch b (256 threads == NB)
    const int b = threadIdx.x;
    float pen = 0.0f;
    {
        const float outw = out[1 + b];   // cond ? wgt : 0
        const float dsq[3] = {g_part[b * 3 + 0], g_part[b * 3 + 1], g_part[b * 3 + 2]};
        const int nqm = g_neq[b];
        #pragma unroll
        for (int j = 0; j < 3; j++) {
            float img_diff = sqrtf(dsq[j]) + 1e-10f;
            float ratio = (1.0f - g_cos[b * 3 + j]) / img_diff;  // LIP = 0
            float term = fmaxf(ratio, 0.0f) * outw;              // SQUARED = false
            if ((nqm >> j) & 1) pen += term;                     // outw==0 covers !cond
        }
    }

    // Reset scratch for the next graph replay (deterministic state).
    g_part[b * 3 + 0] = 0.f;
    g_part[b * 3 + 1] = 0.f;
    g_part[b * 3 + 2] = 0.f;
    g_neq[b] = 0;

    #pragma unroll
    for (int off = 16; off; off >>= 1)
        pen += __shfl_down_sync(0xffffffffu, pen, off);

    __shared__ float smr[TPB / 32];
    if (l == 0) smr[w] = pen;
    __syncthreads();
    if (threadIdx.x == 0) {
        float s = 0.f;
        #pragma unroll
        for (int k = 0; k < TPB / 32; k++) s += smr[k];
        out[0] = s * (1.0f / (float)NB);   // LAMB_LIP = 1
        g_ctr = 0;                          // reset for next replay
    }
}

extern "C" void kernel_launch(void* const* d_in, const int* in_sizes, int n_in,
                              void* d_out, int out_size) {
    const float4* img = (const float4*)d_in[0];
    const float* feat = (const float*)d_in[1];
    const float* feat_norm = (const float*)d_in[2];
    float* out = (float*)d_out;

    fused_kernel<<<GRID, TPB>>>(img, feat, feat_norm, out);
}

// round 15
// speedup vs baseline: 1.0714x; 1.0714x over previous
#include <cuda_runtime.h>
#include <math.h>

// Shapes
#define NB 256            // batch
#define NF 4              // frames
#define PIX4 9408         // float4 per frame (3*112*112/4)
#define TPB 256
// TOT = 256*9408 = 2408448 = 784 * 3072 exactly
#define CH 3072           // float4 per block (12 steps of 256)
#define GRID 784          // <= 888 (148 SMs * 6 CTAs) — one wave at occ 6

// Scratch. g_part/g_neq: zero at process start; epilogue re-zeroes after use.
__device__ float g_part[NB * 3];
__device__ int   g_neq[NB];
__device__ float g_cos[NB * 3];
__device__ int   g_ctr;

__global__ void __launch_bounds__(TPB, 6)
fused_kernel(const float4* __restrict__ img,
             const float* __restrict__ feat,
             const float* __restrict__ feat_norm,
             float* __restrict__ out) {
    __shared__ float sm7[7][TPB / 32];
    __shared__ int   smn[TPB / 32];
    __shared__ int   s_last;

    const int w = threadIdx.x >> 5;
    const int l = threadIdx.x & 31;

    // ---------------- feat prelude (blocks 0..255 only) -------------------
    if (blockIdx.x < NB) {
        const int b = blockIdx.x;
        const float* fb = feat + (size_t)b * (NF * 512);

        float n0 = 0.f, n1 = 0.f, n2 = 0.f, n3 = 0.f;
        float d01 = 0.f, d12 = 0.f, d23 = 0.f;
        #pragma unroll
        for (int k = 0; k < 2; k++) {
            int i = threadIdx.x + k * TPB;
            float a = fb[i];
            float c = fb[512 + i];
            float d = fb[1024 + i];
            float e = fb[1536 + i];
            n0 += a * a; n1 += c * c; n2 += d * d; n3 += e * e;
            d01 += a * c; d12 += c * d; d23 += d * e;
        }
        #pragma unroll
        for (int off = 16; off; off >>= 1) {
            n0  += __shfl_down_sync(0xffffffffu, n0,  off);
            n1  += __shfl_down_sync(0xffffffffu, n1,  off);
            n2  += __shfl_down_sync(0xffffffffu, n2,  off);
            n3  += __shfl_down_sync(0xffffffffu, n3,  off);
            d01 += __shfl_down_sync(0xffffffffu, d01, off);
            d12 += __shfl_down_sync(0xffffffffu, d12, off);
            d23 += __shfl_down_sync(0xffffffffu, d23, off);
        }
        if (l == 0) {
            sm7[0][w] = n0;  sm7[1][w] = n1;  sm7[2][w] = n2;  sm7[3][w] = n3;
            sm7[4][w] = d01; sm7[5][w] = d12; sm7[6][w] = d23;
        }
        __syncthreads();
        if (threadIdx.x == 0) {
            float v[7];
            #pragma unroll
            for (int j = 0; j < 7; j++) {
                float s = 0.f;
                #pragma unroll
                for (int k = 0; k < TPB / 32; k++) s += sm7[j][k];
                v[j] = s;
            }
            float na[4];
            #pragma unroll
            for (int j = 0; j < 4; j++) na[j] = fmaxf(sqrtf(v[j]), 1e-8f);
            #pragma unroll
            for (int j = 0; j < 3; j++)
                g_cos[b * 3 + j] = v[4 + j] / (na[j] * na[j + 1]);

            const float fn0 = feat_norm[b * NF];     // feat_norm[b,0,0]
            const bool cond = fn0 > 0.0f;            // TAO = 0
            const float wgt = 1.0f / (expf(fn0) + 1e-10f);
            out[1 + b] = cond ? wgt : 0.0f;          // also encodes cond (wgt>0)
        }
        __syncthreads();   // sm7 reused below
    }

    // ---------------- img chunk: <=2 single-batch ranges ------------------
    {
        const int start = blockIdx.x * CH;
        const int endc = start + CH;
        int r0 = start;
        int bcur = start / PIX4;

        while (r0 < endc) {
            const int r1 = min(endc, (bcur + 1) * PIX4);
            const float4* base = img + (size_t)3 * bcur * PIX4;

            float s1 = 0.f, s2 = 0.f, s3 = 0.f;
            unsigned m1 = 0, m2 = 0, m3 = 0;

            for (int i = r0 + threadIdx.x; i < r1; i += TPB) {
                float4 f0 = __ldcs(base + i);
                float4 f1 = __ldcs(base + i + PIX4);
                float4 f2 = __ldcs(base + i + 2 * PIX4);
                float4 f3 = __ldcs(base + i + 3 * PIX4);

                float dx, dy, dz, dw;
                dx = f1.x - f0.x; dy = f1.y - f0.y; dz = f1.z - f0.z; dw = f1.w - f0.w;
                s1 += dx * dx + dy * dy + dz * dz + dw * dw;
                dx = f2.x - f1.x; dy = f2.y - f1.y; dz = f2.z - f1.z; dw = f2.w - f1.w;
                s2 += dx * dx + dy * dy + dz * dz + dw * dw;
                dx = f3.x - f2.x; dy = f3.y - f2.y; dz = f3.z - f2.z; dw = f3.w - f2.w;
                s3 += dx * dx + dy * dy + dz * dz + dw * dw;

                // neq vs frame 0, bitwise (input has no NaN / +-0 collisions)
                m1 |= (__float_as_uint(f1.x) ^ __float_as_uint(f0.x)) |
                      (__float_as_uint(f1.y) ^ __float_as_uint(f0.y)) |
                      (__float_as_uint(f1.z) ^ __float_as_uint(f0.z)) |
                      (__float_as_uint(f1.w) ^ __float_as_uint(f0.w));
                m2 |= (__float_as_uint(f2.x) ^ __float_as_uint(f0.x)) |
                      (__float_as_uint(f2.y) ^ __float_as_uint(f0.y)) |
                      (__float_as_uint(f2.z) ^ __float_as_uint(f0.z)) |
                      (__float_as_uint(f2.w) ^ __float_as_uint(f0.w));
                m3 |= (__float_as_uint(f3.x) ^ __float_as_uint(f0.x)) |
                      (__float_as_uint(f3.y) ^ __float_as_uint(f0.y)) |
                      (__float_as_uint(f3.z) ^ __float_as_uint(f0.z)) |
                      (__float_as_uint(f3.w) ^ __float_as_uint(f0.w));
            }

            int mp = (m1 ? 1 : 0) | (m2 ? 2 : 0) | (m3 ? 4 : 0);
            #pragma unroll
            for (int off = 16; off; off >>= 1) {
                s1 += __shfl_down_sync(0xffffffffu, s1, off);
                s2 += __shfl_down_sync(0xffffffffu, s2, off);
                s3 += __shfl_down_sync(0xffffffffu, s3, off);
                mp |= __shfl_down_sync(0xffffffffu, mp, off);
            }
            if (l == 0) { sm7[0][w] = s1; sm7[1][w] = s2; sm7[2][w] = s3; smn[w] = mp; }
            __syncthreads();
            if (threadIdx.x == 0) {
                float v0 = 0.f, v1 = 0.f, v2 = 0.f;
                int nq = 0;
                #pragma unroll
                for (int k = 0; k < TPB / 32; k++) {
                    v0 += sm7[0][k]; v1 += sm7[1][k]; v2 += sm7[2][k];
                    nq |= smn[k];
                }
                atomicAdd(&g_part[bcur * 3 + 0], v0);
                atomicAdd(&g_part[bcur * 3 + 1], v1);
                atomicAdd(&g_part[bcur * 3 + 2], v2);
                atomicOr(&g_neq[bcur], nq);
            }
            __syncthreads();   // smem reuse if a 2nd range follows
            r0 = r1;
            bcur++;
        }
    }

    // ---------------- elect last-finished block for the epilogue ----------
    if (threadIdx.x == 0) {
        __threadfence();
        int old = atomicAdd(&g_ctr, 1);
        s_last = (old == GRID - 1) ? 1 : 0;
    }
    __syncthreads();
    if (!s_last) return;

    __threadfence();  // acquire: all other blocks' atomics/stores visible

    // thread b handles batch b (256 threads == NB)
    const int b = threadIdx.x;
    float pen = 0.0f;
    {
        const float outw = out[1 + b];   // cond ? wgt : 0
        const float dsq[3] = {g_part[b * 3 + 0], g_part[b * 3 + 1], g_part[b * 3 + 2]};
        const int nqm = g_neq[b];
        #pragma unroll
        for (int j = 0; j < 3; j++) {
            float img_diff = sqrtf(dsq[j]) + 1e-10f;
            float ratio = (1.0f - g_cos[b * 3 + j]) / img_diff;  // LIP = 0
            float term = fmaxf(ratio, 0.0f) * outw;              // SQUARED = false
            if ((nqm >> j) & 1) pen += term;                     // outw==0 covers !cond
        }
    }

    // Reset scratch for the next graph replay (deterministic state).
    g_part[b * 3 + 0] = 0.f;
    g_part[b * 3 + 1] = 0.f;
    g_part[b * 3 + 2] = 0.f;
    g_neq[b] = 0;

    #pragma unroll
    for (int off = 16; off; off >>= 1)
        pen += __shfl_down_sync(0xffffffffu, pen, off);

    __shared__ float smr[TPB / 32];
    if (l == 0) smr[w] = pen;
    __syncthreads();
    if (threadIdx.x == 0) {
        float s = 0.f;
        #pragma unroll
        for (int k = 0; k < TPB / 32; k++) s += smr[k];
        out[0] = s * (1.0f / (float)NB);   // LAMB_LIP = 1
        g_ctr = 0;                          // reset for next replay
    }
}

extern "C" void kernel_launch(void* const* d_in, const int* in_sizes, int n_in,
                              void* d_out, int out_size) {
    const float4* img = (const float4*)d_in[0];
    const float* feat = (const float*)d_in[1];
    const float* feat_norm = (const float*)d_in[2];
    float* out = (float*)d_out;

    fused_kernel<<<GRID, TPB>>>(img, feat, feat_norm, out);
}